// round 14
// baseline (speedup 1.0000x reference)
#include <cuda_runtime.h>
#include <cuda_fp16.h>
#include <stdint.h>

#define NATOMS 10000
#define NPAD   10112   // NATOMS rounded up to 32/64; tail rows zeroed
#define F      128
#define NEDGES 640000
#define CAP    256     // per-node bucket capacity (deg ~ Poisson(64); P(>256) ~ 1e-80)

typedef unsigned long long u64_t;

// Scratch (static; no allocations allowed).
// g_deg is zero at module load and re-zeroed in the fused kernel's phase 0
// each call, so prebuild_kernel can start its atomic histogram immediately.
__device__ __align__(16) __half g_X16[NPAD * F];     // feat fp16 (row stride 128)
__device__ __align__(16) __half g_W16[384 * F];      // folded weights fp16 [k][n]
__device__ __align__(16) int    g_deg[NATOMS];       // in-degree (also fill cursor)
__device__ int   g_csr[NATOMS * CAP];                // src indices bucketed by dst
__device__ float g_c[F];                             // b_msg @ Wu_bot (fp32)

// ---------------------------------------------------------------------------
// Fused pre+build: every block does fp16 convert AND 2 edges/thread of the
// bucket build; blocks 625..753 also fold weights. 1250*256*2 == NEDGES.
// ---------------------------------------------------------------------------
__global__ void __launch_bounds__(256) prebuild_kernel(const float* __restrict__ feat,
                                                       const void*  __restrict__ ei,
                                                       const float* __restrict__ W_msg,
                                                       const float* __restrict__ b_msg,
                                                       const float* __restrict__ W_upd) {
    int b = blockIdx.x, t = threadIdx.x;
    int gi = b * 256 + t;

    // ---- dtype detect (per block, cheap) ----
    __shared__ int s_is64;
    if (t == 0) {
        const long long* p = (const long long*)ei;
        int is64 = 1;
        for (int k = 0; k < 8; ++k) {
            long long v = p[k];
            if (v < 0 || v >= NATOMS) { is64 = 0; break; }
        }
        s_is64 = is64;
    }

    {   // fp32 -> fp16: float4 -> 4 halves (one uint2), row stride 128 halves
        float4 v = __ldg((const float4*)feat + gi);
        __half2 h0 = __float22half2_rn(make_float2(v.x, v.y));
        __half2 h1 = __float22half2_rn(make_float2(v.z, v.w));
        uint2 p;
        p.x = *(unsigned*)&h0;
        p.y = *(unsigned*)&h1;
        ((uint2*)g_X16)[gi] = p;                     // gi == row*32 + seg exactly
    }
    // zero tail rows (rows 10000..10111): 112*32 = 3584 uint2
    if (gi < 3584) ((uint2*)g_X16)[NATOMS * 32 + gi] = make_uint2(0u, 0u);

    __syncthreads();
    // ---- edge-bucket build: 2 edges/thread, all blocks ----
    {
        int base = gi * 2;
        int s0, s1, d0, d1;
        if (s_is64) {
            const long long* ps = (const long long*)ei;
            const long long* pd = ps + NEDGES;
            s0 = (int)ps[base]; s1 = (int)ps[base + 1];
            d0 = (int)pd[base]; d1 = (int)pd[base + 1];
        } else {
            int2 sv = ((const int2*)((const int*)ei))[gi];
            int2 dv = ((const int2*)((const int*)ei + NEDGES))[gi];
            s0 = sv.x; s1 = sv.y;
            d0 = dv.x; d1 = dv.y;
        }
        int p0 = atomicAdd(&g_deg[d0], 1);
        int p1 = atomicAdd(&g_deg[d1], 1);
        g_csr[d0 * CAP + p0] = s0;
        g_csr[d1 * CAP + p1] = s1;
    }

    if (b >= 625 && b < 754) {
        // ---- weight fold ----
        int i = b - 625;                              // 0..128
        int j = t & 127, half = t >> 7;
        if (i < 128) {
            float acc = 0.f;
            if (half == 0) {
#pragma unroll 8
                for (int k = 0; k < 128; ++k)
                    acc += W_msg[i * F + k] * W_upd[(128 + k) * F + j];          // Wt row i
                g_W16[(128 + i) * F + j] = __float2half(acc);
            } else {
#pragma unroll 8
                for (int k = 0; k < 128; ++k)
                    acc += W_msg[(128 + i) * F + k] * W_upd[(128 + k) * F + j]; // Wb row i
                g_W16[(256 + i) * F + j] = __float2half(acc);
            }
        } else {
            for (int r = half * 64; r < half * 64 + 64; ++r)
                g_W16[r * F + j] = __float2half(W_upd[r * F + j]);
            if (half == 0) {
                float c = 0.f;
#pragma unroll 8
                for (int k = 0; k < 128; ++k)
                    c += b_msg[k] * W_upd[(128 + k) * F + j];
                g_c[j] = c;
            }
        }
    }
}

// ---------------------------------------------------------------------------
// fp16 helpers
// ---------------------------------------------------------------------------
__device__ __forceinline__ void acc_h4(float4& acc, uint2 p) {
    __half2 h0 = *(__half2*)&p.x;
    __half2 h1 = *(__half2*)&p.y;
    float2 f0 = __half22float2(h0);
    float2 f1 = __half22float2(h1);
    acc.x += f0.x; acc.y += f0.y; acc.z += f1.x; acc.w += f1.y;
}
__device__ __forceinline__ uint2 pack_h4(float4 v) {
    __half2 h0 = __float22half2_rn(make_float2(v.x, v.y));
    __half2 h1 = __float22half2_rn(make_float2(v.z, v.w));
    uint2 p;
    p.x = *(unsigned*)&h0;
    p.y = *(unsigned*)&h1;
    return p;
}

// ---------------------------------------------------------------------------
// MMA helpers
// ---------------------------------------------------------------------------
__device__ __forceinline__ void ldsm_x4(uint32_t r[4], uint32_t addr) {
    asm volatile("ldmatrix.sync.aligned.m8n8.x4.shared.b16 {%0,%1,%2,%3}, [%4];"
                 : "=r"(r[0]), "=r"(r[1]), "=r"(r[2]), "=r"(r[3]) : "r"(addr));
}
__device__ __forceinline__ void ldsm_x4_t(uint32_t r[4], uint32_t addr) {
    asm volatile("ldmatrix.sync.aligned.m8n8.x4.trans.shared.b16 {%0,%1,%2,%3}, [%4];"
                 : "=r"(r[0]), "=r"(r[1]), "=r"(r[2]), "=r"(r[3]) : "r"(addr));
}
__device__ __forceinline__ void mma16816(float d[4], const uint32_t a[4],
                                         uint32_t b0, uint32_t b1) {
    asm volatile("mma.sync.aligned.m16n8k16.row.col.f32.f16.f16.f32 "
                 "{%0,%1,%2,%3}, {%4,%5,%6,%7}, {%8,%9}, {%0,%1,%2,%3};"
                 : "+f"(d[0]), "+f"(d[1]), "+f"(d[2]), "+f"(d[3])
                 : "r"(a[0]), "r"(a[1]), "r"(a[2]), "r"(a[3]), "r"(b0), "r"(b1));
}

// ---------------------------------------------------------------------------
// Fused gather+GEMM: 32 rows x 128 cols per block, 256 threads (8 warps,
// warp = 16x32), grid = 316 fine tiles (smooth wave tail; gather L2 phases
// of some blocks overlap MMA phases of others).
// Phase 0: stage own feat rows to smem X tile, read+clear own g_deg rows.
// Phase 1: warp-per-node gather (4 nodes/warp) -> S and deg*feat written
//          DIRECTLY into the smem X tile (no global round trip).
// Phase 2: tensor-core GEMM, A from persistent smem X (pitch 392 halves,
//          odd 16B-pitch -> conflict-free ldmatrix), W double-buffered.
// Smem: Xs 32*392*2 = 25088 B, Ws 2*64*136*2 = 34816 B, total 59904 B.
// ---------------------------------------------------------------------------
#define XSP 392
#define WPITCH 136
#define FUSED_SMEM_BYTES (32 * XSP * 2 + 2 * 64 * WPITCH * 2)

__global__ void __launch_bounds__(256) fused_kernel(const float* __restrict__ b_upd,
                                                    float* __restrict__ out) {
    extern __shared__ __align__(16) __half smem[];
    __half* Xs = smem;                               // 32 x 392
    __half* WsBuf[2] = { smem + 32 * XSP, smem + 32 * XSP + 64 * WPITCH };
    __shared__ int s_deg[32];

    int tid  = threadIdx.x;
    int lane = tid & 31, wid = tid >> 5;
    int wm = wid >> 2;               // 0..1 -> rows wm*16
    int wn = wid & 3;                // 0..3 -> cols wn*32
    int bm = blockIdx.x * 32;

    // ---- Phase 0: stage own feat rows (32 x 16 uint4) + deg read/clear ----
#pragma unroll
    for (int i = 0; i < 2; ++i) {
        int idx = tid + i * 256;
        int row = idx >> 4, seg = idx & 15;
        uint4 v = __ldg((const uint4*)g_X16 + (bm + row) * 16 + seg);
        *(uint4*)&Xs[row * XSP + seg * 8] = v;
    }
    if (tid < 32) {
        int r = bm + tid;
        int d = (r < NATOMS) ? g_deg[r] : 0;
        s_deg[tid] = d;
        if (r < NATOMS) g_deg[r] = 0;                // restore invariant for next call
    }
    __syncthreads();

    // ---- Phase 1: gather own nodes (warp-per-node, 4 rounds) ----
    const uint2* f16 = (const uint2*)g_X16;          // row stride 32 uint2
#pragma unroll 1
    for (int rd = 0; rd < 4; ++rd) {
        int nb  = wid * 4 + rd;                      // 0..31
        int row = bm + nb;
        int n   = s_deg[nb];
        const int* bucket = g_csr + (row < NATOMS ? row : 0) * CAP;
        int j = 0;
        float4 acc = make_float4(0.f, 0.f, 0.f, 0.f);
        while (n - j >= 32) {
            int s = bucket[j + lane];
#pragma unroll
            for (int i = 0; i < 32; i += 8) {
                uint2 v[8];
#pragma unroll
                for (int q = 0; q < 8; ++q) {
                    int sq = __shfl_sync(0xffffffffu, s, i + q);
                    v[q] = __ldg(f16 + sq * 32 + lane);
                }
#pragma unroll
                for (int q = 0; q < 8; ++q) acc_h4(acc, v[q]);
            }
            j += 32;
        }
        if (j < n) {
            int rem = n - j;
            int s = (lane < rem) ? bucket[j + lane] : 0;
            for (int i = 0; i < rem; ++i) {
                int si = __shfl_sync(0xffffffffu, s, i);
                uint2 v = __ldg(f16 + si * 32 + lane);
                acc_h4(acc, v);
            }
        }
        // S -> smem cols 128..255
        *(uint2*)&Xs[nb * XSP + 128 + lane * 4] = pack_h4(acc);
        // deg*feat -> smem cols 256..383 (from staged feat)
        float d = (float)n;
        uint2 fv = *(uint2*)&Xs[nb * XSP + lane * 4];
        __half2 h0 = *(__half2*)&fv.x;
        __half2 h1 = *(__half2*)&fv.y;
        float2 f0 = __half22float2(h0);
        float2 f1 = __half22float2(h1);
        *(uint2*)&Xs[nb * XSP + 256 + lane * 4] =
            pack_h4(make_float4(f0.x * d, f0.y * d, f1.x * d, f1.y * d));
    }

    // ---- Phase 2: GEMM. A from smem Xs; W double-buffered from global. ----
    float acc[4][4];
#pragma unroll
    for (int nt = 0; nt < 4; ++nt)
#pragma unroll
        for (int q = 0; q < 4; ++q) acc[nt][q] = 0.f;

    uint4 wv[4];
    auto loadW = [&](int c) {
#pragma unroll
        for (int i = 0; i < 4; ++i) {                // 64 k-rows x 16 uint4
            int idx = tid + i * 256;
            int row = idx >> 4, seg = idx & 15;
            wv[i] = __ldg((const uint4*)g_W16 + (c * 64 + row) * 16 + seg);
        }
    };
    auto storeW = [&](int buf) {
        __half* Wp = WsBuf[buf];
#pragma unroll
        for (int i = 0; i < 4; ++i) {
            int idx = tid + i * 256;
            int row = idx >> 4, seg = idx & 15;
            *(uint4*)&Wp[row * WPITCH + seg * 8] = wv[i];
        }
    };

    loadW(0);
    storeW(0);
    __syncthreads();                                 // covers phase-1 Xs writes + W0
#pragma unroll 1
    for (int c = 0; c < 6; ++c) {
        if (c < 5) loadW(c + 1);                     // prefetch (regs)
        const __half* Wp = WsBuf[c & 1];
#pragma unroll
        for (int ks = 0; ks < 4; ++ks) {
            uint32_t a[4];
            int arow = wm * 16 + (lane & 15);
            int acol = c * 64 + ks * 16 + ((lane >> 4) << 3);
            ldsm_x4(a, (uint32_t)__cvta_generic_to_shared(&Xs[arow * XSP + acol]));
            uint32_t bfr[2][4];
            int krow = ks * 16 + (lane & 7) + (((lane >> 3) & 1) << 3);
            int noff = ((lane >> 4) << 3);
#pragma unroll
            for (int nt4 = 0; nt4 < 2; ++nt4) {
                ldsm_x4_t(bfr[nt4], (uint32_t)__cvta_generic_to_shared(
                    &Wp[krow * WPITCH + wn * 32 + nt4 * 16 + noff]));
            }
#pragma unroll
            for (int nt = 0; nt < 4; ++nt)
                mma16816(acc[nt], a,
                         bfr[nt >> 1][(nt & 1) * 2], bfr[nt >> 1][(nt & 1) * 2 + 1]);
        }
        if (c < 5) { storeW((c + 1) & 1); __syncthreads(); }
    }

    // ---- epilogue: + deg*c + b_upd ----
    int colbase = wn * 32 + (lane & 3) * 2;
    float2 cv[4], bv[4];
#pragma unroll
    for (int nt = 0; nt < 4; ++nt) {
        int col = colbase + nt * 8;
        cv[nt] = make_float2(g_c[col], g_c[col + 1]);
        bv[nt] = make_float2(__ldg(&b_upd[col]), __ldg(&b_upd[col + 1]));
    }
    int l0 = wm * 16 + (lane >> 2);
    int l1 = l0 + 8;
    int row0 = bm + l0, row1 = bm + l1;
    float d0 = (float)s_deg[l0];
    float d1 = (float)s_deg[l1];
#pragma unroll
    for (int nt = 0; nt < 4; ++nt) {
        int col = colbase + nt * 8;
        if (row0 < NATOMS) {
            float2 o;
            o.x = acc[nt][0] + d0 * cv[nt].x + bv[nt].x;
            o.y = acc[nt][1] + d0 * cv[nt].y + bv[nt].y;
            *(float2*)&out[row0 * F + col] = o;
        }
        if (row1 < NATOMS) {
            float2 o;
            o.x = acc[nt][2] + d1 * cv[nt].x + bv[nt].x;
            o.y = acc[nt][3] + d1 * cv[nt].y + bv[nt].y;
            *(float2*)&out[row1 * F + col] = o;
        }
    }
}

// ---------------------------------------------------------------------------
extern "C" void kernel_launch(void* const* d_in, const int* in_sizes, int n_in,
                              void* d_out, int out_size) {
    const float* feat  = (const float*)d_in[0];
    const void*  ei    = d_in[1];
    const float* W_msg = (const float*)d_in[2];
    const float* b_msg = (const float*)d_in[3];
    const float* W_upd = (const float*)d_in[4];
    const float* b_upd = (const float*)d_in[5];
    float*       out   = (float*)d_out;

    static int configured = 0;
    if (!configured) {
        cudaFuncSetAttribute(fused_kernel, cudaFuncAttributeMaxDynamicSharedMemorySize,
                             FUSED_SMEM_BYTES);
        configured = 1;
    }

    prebuild_kernel<<<1250, 256>>>(feat, ei, W_msg, b_msg, W_upd);
    fused_kernel<<<NPAD / 32, 256, FUSED_SMEM_BYTES>>>(b_upd, out);
}

// round 15
// speedup vs baseline: 1.0818x; 1.0818x over previous
#include <cuda_runtime.h>
#include <cuda_fp16.h>
#include <stdint.h>

#define NATOMS 10000
#define NPAD   10112   // NATOMS rounded up to 32; tail rows zeroed
#define F      128
#define NEDGES 640000
#define CAP    256     // per-node bucket capacity (deg ~ Poisson(64); P(>256) ~ 1e-80)

typedef unsigned long long u64_t;

// Scratch (static; no allocations allowed).
// g_deg is zero at module load and re-zeroed at the END of out_gemm each call,
// so prebuild_kernel can start its atomic histogram immediately.
__device__ __align__(16) __half g_X16[NPAD * 384];   // [feat | S | deg*feat] fp16
__device__ __align__(16) __half g_W16[384 * F];      // folded weights fp16 [k][n]
__device__ __align__(16) int    g_deg[NATOMS];       // in-degree (also fill cursor)
__device__ int   g_csr[NATOMS * CAP];                // src indices bucketed by dst
__device__ float g_c[F];                             // b_msg @ Wu_bot (fp32)

// ---------------------------------------------------------------------------
// Fused pre+build. Ordering: edge loads + atomics FIRST (ATOMG latency hides
// under the feat-convert loads), dependent csr stores LAST. is64 detect is
// per-thread (uniform 64B broadcast load) -> no block barrier.
// Blocks 625..753 additionally fold weights. 1250*256*2 == NEDGES exactly.
// ---------------------------------------------------------------------------
__global__ void __launch_bounds__(256) prebuild_kernel(const float* __restrict__ feat,
                                                       const void*  __restrict__ ei,
                                                       const float* __restrict__ W_msg,
                                                       const float* __restrict__ b_msg,
                                                       const float* __restrict__ W_upd) {
    int b = blockIdx.x, t = threadIdx.x;
    int gi = b * 256 + t;

    // ---- dtype detect (per-thread; all threads read the same 64B) ----
    bool is64 = true;
    {
        const long long* p = (const long long*)ei;
#pragma unroll
        for (int k = 0; k < 8; ++k) {
            long long v = p[k];
            if (v < 0 || v >= NATOMS) is64 = false;
        }
    }

    // ---- edge decode + atomics (issued early) ----
    int s0, s1, d0, d1;
    if (is64) {
        const long long* ps = (const long long*)ei;
        const long long* pd = ps + NEDGES;
        int base = gi * 2;
        s0 = (int)ps[base]; s1 = (int)ps[base + 1];
        d0 = (int)pd[base]; d1 = (int)pd[base + 1];
    } else {
        int2 sv = ((const int2*)((const int*)ei))[gi];
        int2 dv = ((const int2*)((const int*)ei + NEDGES))[gi];
        s0 = sv.x; s1 = sv.y;
        d0 = dv.x; d1 = dv.y;
    }
    int p0 = atomicAdd(&g_deg[d0], 1);
    int p1 = atomicAdd(&g_deg[d1], 1);

    // ---- fp32 -> fp16 convert (hides the atomic return latency) ----
    {
        int row = gi >> 5, seg = gi & 31;
        float4 v = __ldg((const float4*)feat + gi);
        __half2 h0 = __float22half2_rn(make_float2(v.x, v.y));
        __half2 h1 = __float22half2_rn(make_float2(v.z, v.w));
        uint2 p;
        p.x = *(unsigned*)&h0;
        p.y = *(unsigned*)&h1;
        ((uint2*)g_X16)[row * 96 + seg] = p;         // 384 halves = 96 uint2 per row
    }
    // zero tail rows (rows 10000..10111, all 384 cols): 112*96 = 10752 uint2
    if (gi < 10752) ((uint2*)g_X16)[NATOMS * 96 + gi] = make_uint2(0u, 0u);

    // ---- dependent bucket stores ----
    g_csr[d0 * CAP + p0] = s0;
    g_csr[d1 * CAP + p1] = s1;

    if (b >= 625 && b < 754) {
        // ---- weight fold ----
        int i = b - 625;                              // 0..128
        int j = t & 127, half = t >> 7;
        if (i < 128) {
            float acc = 0.f;
            if (half == 0) {
#pragma unroll 8
                for (int k = 0; k < 128; ++k)
                    acc += W_msg[i * F + k] * W_upd[(128 + k) * F + j];          // Wt row i
                g_W16[(128 + i) * F + j] = __float2half(acc);
            } else {
#pragma unroll 8
                for (int k = 0; k < 128; ++k)
                    acc += W_msg[(128 + i) * F + k] * W_upd[(128 + k) * F + j]; // Wb row i
                g_W16[(256 + i) * F + j] = __float2half(acc);
            }
        } else {
            for (int r = half * 64; r < half * 64 + 64; ++r)
                g_W16[r * F + j] = __float2half(W_upd[r * F + j]);
            if (half == 0) {
                float c = 0.f;
#pragma unroll 8
                for (int k = 0; k < 128; ++k)
                    c += b_msg[k] * W_upd[(128 + k) * F + j];
                g_c[j] = c;
            }
        }
    }
}

// ---------------------------------------------------------------------------
// Gather: one warp per dst node, fp32 accumulation over fp16 feat rows
// (X16 cols 0..127). Writes S (cols 128..255) and deg*feat (cols 256..383).
// ---------------------------------------------------------------------------
__device__ __forceinline__ void acc_h4(float4& acc, uint2 p) {
    __half2 h0 = *(__half2*)&p.x;
    __half2 h1 = *(__half2*)&p.y;
    float2 f0 = __half22float2(h0);
    float2 f1 = __half22float2(h1);
    acc.x += f0.x; acc.y += f0.y; acc.z += f1.x; acc.w += f1.y;
}
__device__ __forceinline__ uint2 pack_h4(float4 v) {
    __half2 h0 = __float22half2_rn(make_float2(v.x, v.y));
    __half2 h1 = __float22half2_rn(make_float2(v.z, v.w));
    uint2 p;
    p.x = *(unsigned*)&h0;
    p.y = *(unsigned*)&h1;
    return p;
}

__global__ void __launch_bounds__(256) gather_kernel() {
    int warp = (blockIdx.x * blockDim.x + threadIdx.x) >> 5;
    int lane = threadIdx.x & 31;
    if (warp >= NATOMS) return;

    const int* bucket = g_csr + warp * CAP;
    const uint2* f16 = (const uint2*)g_X16;        // row stride 96 uint2; feat = first 32
    int n = g_deg[warp];
    int j = 0;
    float4 acc = make_float4(0.f, 0.f, 0.f, 0.f);

    while (n - j >= 32) {
        int s = bucket[j + lane];
#pragma unroll
        for (int i = 0; i < 32; i += 8) {
            uint2 v[8];
#pragma unroll
            for (int q = 0; q < 8; ++q) {
                int sq = __shfl_sync(0xffffffffu, s, i + q);
                v[q] = __ldg(f16 + sq * 96 + lane);
            }
#pragma unroll
            for (int q = 0; q < 8; ++q) acc_h4(acc, v[q]);
        }
        j += 32;
    }
    if (j < n) {
        int rem = n - j;
        int s = (lane < rem) ? bucket[j + lane] : 0;
        for (int i = 0; i < rem; ++i) {
            int si = __shfl_sync(0xffffffffu, s, i);
            uint2 v = __ldg(f16 + si * 96 + lane);
            acc_h4(acc, v);
        }
    }
    // S -> cols 128..255
    ((uint2*)g_X16)[warp * 96 + 32 + lane] = pack_h4(acc);
    // deg * feat -> cols 256..383
    float d = (float)n;
    uint2 fv = __ldg(f16 + warp * 96 + lane);
    __half2 h0 = *(__half2*)&fv.x;
    __half2 h1 = *(__half2*)&fv.y;
    float2 f0 = __half22float2(h0);
    float2 f1 = __half22float2(h1);
    ((uint2*)g_X16)[warp * 96 + 64 + lane] =
        pack_h4(make_float4(f0.x * d, f0.y * d, f1.x * d, f1.y * d));
}

// ---------------------------------------------------------------------------
// Tensor-core GEMM, 32-row tiles: out = X16 @ W16 + deg*c + b_upd.
// Block: 32 rows x 128 cols, 256 threads (8 warps, warp = 16x32).
// Grid = 316 -> fine tiles smooth the wave tail (was 2x on 10 SMs at 158).
// Double-buffered smem (X and W), one __syncthreads per K-chunk.
// Each block zeroes its own g_deg rows at the end (invariant for prebuild).
// ---------------------------------------------------------------------------
__device__ __forceinline__ void ldsm_x4(uint32_t r[4], uint32_t addr) {
    asm volatile("ldmatrix.sync.aligned.m8n8.x4.shared.b16 {%0,%1,%2,%3}, [%4];"
                 : "=r"(r[0]), "=r"(r[1]), "=r"(r[2]), "=r"(r[3]) : "r"(addr));
}
__device__ __forceinline__ void ldsm_x4_t(uint32_t r[4], uint32_t addr) {
    asm volatile("ldmatrix.sync.aligned.m8n8.x4.trans.shared.b16 {%0,%1,%2,%3}, [%4];"
                 : "=r"(r[0]), "=r"(r[1]), "=r"(r[2]), "=r"(r[3]) : "r"(addr));
}
__device__ __forceinline__ void mma16816(float d[4], const uint32_t a[4],
                                         uint32_t b0, uint32_t b1) {
    asm volatile("mma.sync.aligned.m16n8k16.row.col.f32.f16.f16.f32 "
                 "{%0,%1,%2,%3}, {%4,%5,%6,%7}, {%8,%9}, {%0,%1,%2,%3};"
                 : "+f"(d[0]), "+f"(d[1]), "+f"(d[2]), "+f"(d[3])
                 : "r"(a[0]), "r"(a[1]), "r"(a[2]), "r"(a[3]), "r"(b0), "r"(b1));
}

#define XPITCH 72
#define WPITCH 136
// smem halves: X 2*32*72 = 4608, W 2*64*136 = 17408 -> 22016 halves = 44032 B
#define GEMM_SMEM_BYTES ((2 * 32 * XPITCH + 2 * 64 * WPITCH) * 2)

__global__ void __launch_bounds__(256) out_gemm(const float* __restrict__ b_upd,
                                                float* __restrict__ out) {
    extern __shared__ __align__(16) __half smem[];
    __half* XsBuf[2] = { smem,                smem + 32 * XPITCH };
    __half* WsBuf[2] = { smem + 2 * 32 * XPITCH,
                         smem + 2 * 32 * XPITCH + 64 * WPITCH };

    int tid  = threadIdx.x;
    int lane = tid & 31, wid = tid >> 5;
    int wm = wid >> 2;               // 0..1 -> rows wm*16
    int wn = wid & 3;                // 0..3 -> cols wn*32
    int bm = blockIdx.x * 32;

    float acc[4][4];
#pragma unroll
    for (int nt = 0; nt < 4; ++nt)
#pragma unroll
        for (int q = 0; q < 4; ++q) acc[nt][q] = 0.f;

    // register staging for prefetch
    uint4 xv, wv[4];
    auto loadXW = [&](int c) {
        {   // Xs: 32 rows x 8 uint4 = 256 -> 1 per thread
            int row = tid >> 3, seg = tid & 7;
            xv = __ldg((const uint4*)g_X16 + (u64_t)(bm + row) * 48 + c * 8 + seg);
        }
#pragma unroll
        for (int i = 0; i < 4; ++i) {                   // Ws: 64 k-rows x 16 uint4
            int idx = tid + i * 256;
            int row = idx >> 4, seg = idx & 15;
            wv[i] = __ldg((const uint4*)g_W16 + (c * 64 + row) * 16 + seg);
        }
    };
    auto storeXW = [&](int buf) {
        {
            int row = tid >> 3, seg = tid & 7;
            *(uint4*)&XsBuf[buf][row * XPITCH + seg * 8] = xv;
        }
#pragma unroll
        for (int i = 0; i < 4; ++i) {
            int idx = tid + i * 256;
            int row = idx >> 4, seg = idx & 15;
            *(uint4*)&WsBuf[buf][row * WPITCH + seg * 8] = wv[i];
        }
    };

    loadXW(0);
    storeXW(0);
#pragma unroll 1
    for (int c = 0; c < 6; ++c) {
        __syncthreads();                                 // buf c&1 ready for all
        if (c < 5) loadXW(c + 1);                        // LDG prefetch (regs)
        const __half* Xp = XsBuf[c & 1];
        const __half* Wp = WsBuf[c & 1];
#pragma unroll
        for (int ks = 0; ks < 4; ++ks) {
            uint32_t a[4];
            int arow = wm * 16 + (lane & 15);
            int acol = ks * 16 + ((lane >> 4) << 3);
            ldsm_x4(a, (uint32_t)__cvta_generic_to_shared(&Xp[arow * XPITCH + acol]));
            uint32_t bfr[2][4];
            int krow = ks * 16 + (lane & 7) + (((lane >> 3) & 1) << 3);
            int noff = ((lane >> 4) << 3);
#pragma unroll
            for (int nt4 = 0; nt4 < 2; ++nt4) {
                ldsm_x4_t(bfr[nt4], (uint32_t)__cvta_generic_to_shared(
                    &Wp[krow * WPITCH + wn * 32 + nt4 * 16 + noff]));
            }
#pragma unroll
            for (int nt = 0; nt < 4; ++nt)
                mma16816(acc[nt], a,
                         bfr[nt >> 1][(nt & 1) * 2], bfr[nt >> 1][(nt & 1) * 2 + 1]);
        }
        if (c < 5) storeXW((c + 1) & 1);                 // other buffer: no conflict
    }

    // ---- epilogue: + deg*c + b_upd ----
    int colbase = wn * 32 + (lane & 3) * 2;
    float2 cv[4], bv[4];
#pragma unroll
    for (int nt = 0; nt < 4; ++nt) {
        int col = colbase + nt * 8;
        cv[nt] = make_float2(g_c[col], g_c[col + 1]);
        bv[nt] = make_float2(__ldg(&b_upd[col]), __ldg(&b_upd[col + 1]));
    }
    int row0 = bm + wm * 16 + (lane >> 2);
    int row1 = row0 + 8;
    float d0 = (row0 < NATOMS) ? (float)g_deg[row0] : 0.f;
    float d1 = (row1 < NATOMS) ? (float)g_deg[row1] : 0.f;
#pragma unroll
    for (int nt = 0; nt < 4; ++nt) {
        int col = colbase + nt * 8;
        if (row0 < NATOMS) {
            float2 o;
            o.x = acc[nt][0] + d0 * cv[nt].x + bv[nt].x;
            o.y = acc[nt][1] + d0 * cv[nt].y + bv[nt].y;
            *(float2*)&out[row0 * F + col] = o;
        }
        if (row1 < NATOMS) {
            float2 o;
            o.x = acc[nt][2] + d1 * cv[nt].x + bv[nt].x;
            o.y = acc[nt][3] + d1 * cv[nt].y + bv[nt].y;
            *(float2*)&out[row1 * F + col] = o;
        }
    }

    // ---- restore invariant: zero this block's g_deg rows for the next call ----
    __syncthreads();                                     // all epilogue reads done
    if (tid < 32) {
        int r = bm + tid;
        if (r < NATOMS) g_deg[r] = 0;
    }
}

// ---------------------------------------------------------------------------
extern "C" void kernel_launch(void* const* d_in, const int* in_sizes, int n_in,
                              void* d_out, int out_size) {
    const float* feat  = (const float*)d_in[0];
    const void*  ei    = d_in[1];
    const float* W_msg = (const float*)d_in[2];
    const float* b_msg = (const float*)d_in[3];
    const float* W_upd = (const float*)d_in[4];
    const float* b_upd = (const float*)d_in[5];
    float*       out   = (float*)d_out;

    static int configured = 0;
    if (!configured) {
        cudaFuncSetAttribute(out_gemm, cudaFuncAttributeMaxDynamicSharedMemorySize,
                             GEMM_SMEM_BYTES);
        configured = 1;
    }

    prebuild_kernel<<<1250, 256>>>(feat, ei, W_msg, b_msg, W_upd);
    gather_kernel<<<(NATOMS * 32 + 255) / 256, 256>>>();
    out_gemm<<<NPAD / 32, 256, GEMM_SMEM_BYTES>>>(b_upd, out);
}